// round 1
// baseline (speedup 1.0000x reference)
#include <cuda_runtime.h>
#include <math.h>

// Problem constants (fixed by the reference)
#define TT   1024        // tokens
#define HH   2048        // hidden
#define MI   1408        // moe intermediate
#define EE   32          // routed experts
#define KTOP 6           // experts per token
#define MSHD 2816        // shared intermediate (M * 2)
#define NA   (TT * KTOP) // total assignments = 6144

// ---------------- scratch (static device globals; no allocation) ----------
__device__ float g_act[(size_t)NA * MI];     // silu(gate)*up per assignment   (~34.6 MB)
__device__ float g_y[(size_t)NA * HH];       // weighted down-proj per assign. (~50 MB)
__device__ float g_shact[(size_t)TT * MSHD]; // shared-expert intermediate     (~11.5 MB)
__device__ float g_topkw[NA];                // routing weight per assignment
__device__ int   g_cnt[EE];                  // tokens per expert
__device__ int   g_list[EE * TT];            // assignment rowids per expert

// ---------------- tiny kernels --------------------------------------------
__global__ void zero_cnt_kernel() {
    if (threadIdx.x < EE) g_cnt[threadIdx.x] = 0;
}

// Router: 8 tokens per block (1 warp each). Computes sigmoid scores,
// grouped top-2-sum group scores, top-4 groups, masked top-6 experts,
// and compacts assignments into per-expert lists.
__global__ void router_kernel(const float* __restrict__ x,
                              const float* __restrict__ wr,
                              const float* __restrict__ bias)
{
    __shared__ float s_sfc[8][32];
    __shared__ float s_sc[8][32];
    int warp = threadIdx.x >> 5, lane = threadIdx.x & 31;
    int t = blockIdx.x * 8 + warp;
    const float* xr = x + (size_t)t * HH;

    float acc = 0.f;
#pragma unroll 8
    for (int h = 0; h < HH; ++h) acc = fmaf(xr[h], wr[h * EE + lane], acc);

    float sc = 1.f / (1.f + expf(-acc));
    s_sc[warp][lane]  = sc;
    s_sfc[warp][lane] = sc + bias[lane];
    __syncwarp();

    if (lane == 0) {
        // group scores = sum of top-2 within each group of 4
        float gsc[8];
#pragma unroll
        for (int g = 0; g < 8; ++g) {
            const float* v = &s_sfc[warp][g * 4];
            float m1 = -INFINITY; int i1 = 0;
            for (int j = 0; j < 4; ++j) if (v[j] > m1) { m1 = v[j]; i1 = j; }
            float m2 = -INFINITY;
            for (int j = 0; j < 4; ++j) if (j != i1 && v[j] > m2) m2 = v[j];
            gsc[g] = m1 + m2;
        }
        // top-4 groups
        unsigned gsel = 0;
        for (int it = 0; it < 4; ++it) {
            float best = -INFINITY; int bi = 0;
            for (int g = 0; g < 8; ++g)
                if (!((gsel >> g) & 1) && gsc[g] > best) { best = gsc[g]; bi = g; }
            gsel |= 1u << bi;
        }
        // masked top-6 experts (weights = raw sigmoid scores)
        float msk[32];
        for (int e = 0; e < 32; ++e)
            msk[e] = ((gsel >> (e >> 2)) & 1) ? s_sfc[warp][e] : -INFINITY;
        for (int k = 0; k < KTOP; ++k) {
            float best = -INFINITY; int bi = 0;
            for (int e = 0; e < 32; ++e)
                if (msk[e] > best) { best = msk[e]; bi = e; }
            msk[bi] = -INFINITY;
            int rowid = t * KTOP + k;
            g_topkw[rowid] = s_sc[warp][bi];
            int pos = atomicAdd(&g_cnt[bi], 1);
            g_list[bi * TT + pos] = rowid;
        }
    }
}

// ---------------- generic gathered tiled SGEMM -----------------------------
// C[idx] (+)= op( A[idx/rowDiv] @ B_e ), with per-expert row lists.
// EPI: 0 = store, 1 = store silu(v), 2 = C *= v, 3 = store v*rowScale[idx]
#define BM 128
#define BN 128
#define BK 8

template<int EPI>
__global__ void __launch_bounds__(256)
gemm_kernel(const float* __restrict__ A, const float* __restrict__ Bb,
            float* __restrict__ C,
            const int* __restrict__ list, const int* __restrict__ cntArr,
            const float* __restrict__ rowScale,
            int K, int N, int rowDiv, int fixedCnt)
{
    int e = blockIdx.z;
    int cnt = cntArr ? cntArr[e] : fixedCnt;
    int row0 = blockIdx.y * BM;
    if (row0 >= cnt) return;
    int col0 = blockIdx.x * BN;
    const float* B = Bb + (size_t)e * K * N;

    __shared__ float As[BK][BM];
    __shared__ float Bs[BK][BN];

    int tid = threadIdx.x;
    // A-tile load map: 128 rows x 8 k, one float4 per thread
    int aRowL = tid >> 1;
    int aK    = (tid & 1) * 4;
    int gi = row0 + aRowL;
    const float* Arow = nullptr;
    if (gi < cnt) {
        int idx = list ? list[e * TT + gi] : gi;
        Arow = A + (size_t)(idx / rowDiv) * K;
    }
    // B-tile load map: 8 k x 128 n, one float4 per thread
    int bK = tid >> 5;
    int bN = (tid & 31) * 4;

    int tr = (tid >> 4) * 8;
    int tc = (tid & 15) * 8;

    float acc[8][8];
#pragma unroll
    for (int i = 0; i < 8; ++i)
#pragma unroll
        for (int j = 0; j < 8; ++j) acc[i][j] = 0.f;

    for (int k0 = 0; k0 < K; k0 += BK) {
        float4 av = Arow ? *(const float4*)(Arow + k0 + aK)
                         : make_float4(0.f, 0.f, 0.f, 0.f);
        float4 bv = *(const float4*)(B + (size_t)(k0 + bK) * N + col0 + bN);
        __syncthreads();
        As[aK + 0][aRowL] = av.x;
        As[aK + 1][aRowL] = av.y;
        As[aK + 2][aRowL] = av.z;
        As[aK + 3][aRowL] = av.w;
        *(float4*)&Bs[bK][bN] = bv;
        __syncthreads();
#pragma unroll
        for (int kk = 0; kk < BK; ++kk) {
            float a[8], b[8];
#pragma unroll
            for (int i = 0; i < 8; ++i) a[i] = As[kk][tr + i];
#pragma unroll
            for (int j = 0; j < 8; ++j) b[j] = Bs[kk][tc + j];
#pragma unroll
            for (int i = 0; i < 8; ++i)
#pragma unroll
                for (int j = 0; j < 8; ++j)
                    acc[i][j] = fmaf(a[i], b[j], acc[i][j]);
        }
    }

#pragma unroll
    for (int i = 0; i < 8; ++i) {
        int g = row0 + tr + i;
        if (g >= cnt) continue;
        int idx = list ? list[e * TT + g] : g;
        float* Cr = C + (size_t)idx * N + col0 + tc;
        float s = (EPI == 3) ? rowScale[idx] : 1.f;
#pragma unroll
        for (int j = 0; j < 8; ++j) {
            float v = acc[i][j];
            if      (EPI == 0) Cr[j] = v;
            else if (EPI == 1) Cr[j] = v / (1.f + expf(-v));   // silu
            else if (EPI == 2) Cr[j] *= v;
            else               Cr[j] = v * s;
        }
    }
}

// out[t] += sum_k g_y[t*6+k]   (shared-expert result already in out)
__global__ void add_routed_kernel(float* __restrict__ out) {
    int i = blockIdx.x * blockDim.x + threadIdx.x;
    if (i >= TT * HH / 4) return;
    int t = i / (HH / 4);
    int c = i % (HH / 4);
    float4 o = ((float4*)out)[i];
#pragma unroll
    for (int k = 0; k < KTOP; ++k) {
        float4 v = ((const float4*)(g_y + (size_t)(t * KTOP + k) * HH))[c];
        o.x += v.x; o.y += v.y; o.z += v.z; o.w += v.w;
    }
    ((float4*)out)[i] = o;
}

// ---------------- launch ----------------------------------------------------
extern "C" void kernel_launch(void* const* d_in, const int* in_sizes, int n_in,
                              void* d_out, int out_size)
{
    const float* x      = (const float*)d_in[0];
    const float* wr     = (const float*)d_in[1];
    const float* bias   = (const float*)d_in[2];
    const float* gate_w = (const float*)d_in[3];
    const float* up_w   = (const float*)d_in[4];
    const float* down_w = (const float*)d_in[5];
    const float* shg    = (const float*)d_in[6];
    const float* shu    = (const float*)d_in[7];
    const float* shd    = (const float*)d_in[8];
    float* out = (float*)d_out;

    void *p_act, *p_y, *p_shact, *p_w, *p_cnt, *p_list;
    cudaGetSymbolAddress(&p_act,   g_act);
    cudaGetSymbolAddress(&p_y,     g_y);
    cudaGetSymbolAddress(&p_shact, g_shact);
    cudaGetSymbolAddress(&p_w,     g_topkw);
    cudaGetSymbolAddress(&p_cnt,   g_cnt);
    cudaGetSymbolAddress(&p_list,  g_list);

    zero_cnt_kernel<<<1, 32>>>();
    router_kernel<<<TT / 8, 256>>>(x, wr, bias);

    // routed experts: act = silu(x@gate) * (x@up); y = (act@down) * w
    gemm_kernel<1><<<dim3(MI / BN, TT / BM, EE), 256>>>(
        x, gate_w, (float*)p_act, (const int*)p_list, (const int*)p_cnt,
        nullptr, HH, MI, KTOP, 0);
    gemm_kernel<2><<<dim3(MI / BN, TT / BM, EE), 256>>>(
        x, up_w, (float*)p_act, (const int*)p_list, (const int*)p_cnt,
        nullptr, HH, MI, KTOP, 0);
    gemm_kernel<3><<<dim3(HH / BN, TT / BM, EE), 256>>>(
        (const float*)p_act, down_w, (float*)p_y, (const int*)p_list,
        (const int*)p_cnt, (const float*)p_w, MI, HH, 1, 0);

    // shared experts: out = (silu(x@shg) * (x@shu)) @ shd
    gemm_kernel<1><<<dim3(MSHD / BN, TT / BM, 1), 256>>>(
        x, shg, (float*)p_shact, nullptr, nullptr, nullptr, HH, MSHD, 1, TT);
    gemm_kernel<2><<<dim3(MSHD / BN, TT / BM, 1), 256>>>(
        x, shu, (float*)p_shact, nullptr, nullptr, nullptr, HH, MSHD, 1, TT);
    gemm_kernel<0><<<dim3(HH / BN, TT / BM, 1), 256>>>(
        (const float*)p_shact, shd, out, nullptr, nullptr, nullptr, MSHD, HH, 1, TT);

    // out += routed combination
    add_routed_kernel<<<(TT * HH / 4 + 255) / 256, 256>>>(out);
}

// round 2
// speedup vs baseline: 2.3868x; 2.3868x over previous
#include <cuda_runtime.h>
#include <math.h>

// Problem constants (fixed by the reference)
#define TT   1024        // tokens
#define HH   2048        // hidden
#define MI   1408        // moe intermediate
#define EE   32          // routed experts
#define KTOP 6           // experts per token
#define MSHD 2816        // shared intermediate (M * 2)
#define NA   (TT * KTOP) // total assignments = 6144

// ---------------- scratch (static device globals; no allocation) ----------
__device__ float g_act[(size_t)NA * MI];     // silu(gate)*up per assignment
__device__ float g_y[(size_t)NA * HH];       // weighted down-proj per assign.
__device__ float g_shact[(size_t)TT * MSHD]; // shared-expert intermediate
__device__ float g_topkw[NA];                // routing weight per assignment
__device__ int   g_cnt[EE];                  // tokens per expert
__device__ int   g_list[EE * TT];            // assignment rowids per expert

// ---------------- tiny kernels --------------------------------------------
__global__ void zero_cnt_kernel() {
    if (threadIdx.x < EE) g_cnt[threadIdx.x] = 0;
}

__global__ void router_kernel(const float* __restrict__ x,
                              const float* __restrict__ wr,
                              const float* __restrict__ bias)
{
    __shared__ float s_sfc[8][32];
    __shared__ float s_sc[8][32];
    int warp = threadIdx.x >> 5, lane = threadIdx.x & 31;
    int t = blockIdx.x * 8 + warp;
    const float* xr = x + (size_t)t * HH;

    float acc = 0.f;
#pragma unroll 8
    for (int h = 0; h < HH; ++h) acc = fmaf(xr[h], wr[h * EE + lane], acc);

    float sc = 1.f / (1.f + expf(-acc));
    s_sc[warp][lane]  = sc;
    s_sfc[warp][lane] = sc + bias[lane];
    __syncwarp();

    if (lane == 0) {
        float gsc[8];
#pragma unroll
        for (int g = 0; g < 8; ++g) {
            const float* v = &s_sfc[warp][g * 4];
            float m1 = -INFINITY; int i1 = 0;
            for (int j = 0; j < 4; ++j) if (v[j] > m1) { m1 = v[j]; i1 = j; }
            float m2 = -INFINITY;
            for (int j = 0; j < 4; ++j) if (j != i1 && v[j] > m2) m2 = v[j];
            gsc[g] = m1 + m2;
        }
        unsigned gsel = 0;
        for (int it = 0; it < 4; ++it) {
            float best = -INFINITY; int bi = 0;
            for (int g = 0; g < 8; ++g)
                if (!((gsel >> g) & 1) && gsc[g] > best) { best = gsc[g]; bi = g; }
            gsel |= 1u << bi;
        }
        float msk[32];
        for (int e = 0; e < 32; ++e)
            msk[e] = ((gsel >> (e >> 2)) & 1) ? s_sfc[warp][e] : -INFINITY;
        for (int k = 0; k < KTOP; ++k) {
            float best = -INFINITY; int bi = 0;
            for (int e = 0; e < 32; ++e)
                if (msk[e] > best) { best = msk[e]; bi = e; }
            msk[bi] = -INFINITY;
            int rowid = t * KTOP + k;
            g_topkw[rowid] = s_sc[warp][bi];
            int pos = atomicAdd(&g_cnt[bi], 1);
            g_list[bi * TT + pos] = rowid;
        }
    }
}

// ---------------- tf32 tensor-core gathered GEMM ---------------------------
// Tiles: BM=128, BN=128, BK=16; 8 warps (2m x 4n), warp tile 64x32.
// A in SMEM: per-row k-permuted layout (group = k%4, within = k/4) with
// XOR-swizzle on the group so A fragments load as single LDS.128 per row.
// B in SMEM: [k][n] with pad 132 (conflict-free scalar LDS).
// EPI: 0 = store, 1 = silu, 2 = multiply-into-C, 3 = scale by rowScale[idx]

__device__ __forceinline__ unsigned f2tf(float f) {
    unsigned r; asm("cvt.rna.tf32.f32 %0, %1;" : "=r"(r) : "f"(f)); return r;
}

__device__ __forceinline__ void mma_tf32(float* c,
    unsigned a0, unsigned a1, unsigned a2, unsigned a3,
    unsigned b0, unsigned b1)
{
    asm volatile(
      "mma.sync.aligned.m16n8k8.row.col.f32.tf32.tf32.f32 "
      "{%0,%1,%2,%3}, {%4,%5,%6,%7}, {%8,%9}, {%0,%1,%2,%3};"
      : "+f"(c[0]), "+f"(c[1]), "+f"(c[2]), "+f"(c[3])
      : "r"(a0), "r"(a1), "r"(a2), "r"(a3), "r"(b0), "r"(b1));
}

#define BPAD 132

template<int EPI>
__global__ void __launch_bounds__(256)
mma_gemm(const float* __restrict__ A, const float* __restrict__ Bb,
         float* __restrict__ C,
         const int* __restrict__ list, const int* __restrict__ cntArr,
         const float* __restrict__ rowScale,
         int K, int N, int rowDiv, int fixedCnt)
{
    int e = blockIdx.z;
    int cnt = cntArr ? cntArr[e] : fixedCnt;
    int row0 = blockIdx.y * 128;
    if (row0 >= cnt) return;
    int col0 = blockIdx.x * 128;
    const float* B = Bb + (size_t)e * K * N;

    __shared__ __align__(16) unsigned As[2][128 * 16];
    __shared__ __align__(16) unsigned Bs[2][16 * BPAD];

    int tid  = threadIdx.x;
    int lane = tid & 31, warp = tid >> 5;
    int l4 = lane & 3, g = lane >> 2;
    int wm = (warp & 1) * 64;
    int wn = (warp >> 1) * 32;

    // ---- global load maps ----
    // A: slot s in [0,512): row = s>>2, j = s&3; thread handles s=tid, tid+256
    int arow_l = tid >> 2;      // 0..63
    int aj     = tid & 3;       // k-group (global k = k0 + 4*aj)
    const float* Arow[2];
#pragma unroll
    for (int h = 0; h < 2; ++h) {
        int gi = row0 + arow_l + h * 64;
        const float* p = nullptr;
        if (gi < cnt) {
            int idx = list ? list[e * TT + gi] : gi;
            p = A + (size_t)(idx / rowDiv) * K;
        }
        Arow[h] = p;
    }
    // B: slot s: k = s>>5 (0..15 over two slots), ng = s&31
    int bk = tid >> 5;          // 0..7 (+8 for second slot)
    int bn = (tid & 31) * 4;

    float acc[4][4][4];
#pragma unroll
    for (int a = 0; a < 4; ++a)
#pragma unroll
        for (int b = 0; b < 4; ++b)
#pragma unroll
            for (int c = 0; c < 4; ++c) acc[a][b][c] = 0.f;

    const int nIter = K / 16;

    // ---- prologue: tile 0 ----
    {
        float4 av[2], bv[2];
#pragma unroll
        for (int h = 0; h < 2; ++h) {
            av[h] = Arow[h] ? *(const float4*)(Arow[h] + 4 * aj)
                            : make_float4(0.f, 0.f, 0.f, 0.f);
            bv[h] = *(const float4*)(B + (size_t)(bk + 8 * h) * N + col0 + bn);
        }
#pragma unroll
        for (int h = 0; h < 2; ++h) {
            int row = arow_l + h * 64;
            unsigned* dst = &As[0][row * 16];
            int sw = row & 3;
            dst[((0 ^ sw) << 2) + aj] = f2tf(av[h].x);
            dst[((1 ^ sw) << 2) + aj] = f2tf(av[h].y);
            dst[((2 ^ sw) << 2) + aj] = f2tf(av[h].z);
            dst[((3 ^ sw) << 2) + aj] = f2tf(av[h].w);
            unsigned* bd = &Bs[0][(bk + 8 * h) * BPAD + bn];
            bd[0] = f2tf(bv[h].x); bd[1] = f2tf(bv[h].y);
            bd[2] = f2tf(bv[h].z); bd[3] = f2tf(bv[h].w);
        }
    }
    __syncthreads();

    for (int it = 0; it < nIter; ++it) {
        int p = it & 1;
        bool more = (it + 1 < nIter);
        float4 av[2], bv[2];
        if (more) {
            int k0 = (it + 1) * 16;
#pragma unroll
            for (int h = 0; h < 2; ++h) {
                av[h] = Arow[h] ? *(const float4*)(Arow[h] + k0 + 4 * aj)
                                : make_float4(0.f, 0.f, 0.f, 0.f);
                bv[h] = *(const float4*)(B + (size_t)(k0 + bk + 8 * h) * N + col0 + bn);
            }
        }

        // ---- compute on buffer p ----
        unsigned ar[4][2][4];
#pragma unroll
        for (int mf = 0; mf < 4; ++mf)
#pragma unroll
            for (int rs = 0; rs < 2; ++rs) {
                int row = wm + mf * 16 + g + rs * 8;
                uint4 v = *(const uint4*)&As[p][row * 16 + ((l4 ^ (row & 3)) << 2)];
                ar[mf][rs][0] = v.x; ar[mf][rs][1] = v.y;
                ar[mf][rs][2] = v.z; ar[mf][rs][3] = v.w;
            }
        unsigned br[4][4];
#pragma unroll
        for (int nf = 0; nf < 4; ++nf)
#pragma unroll
            for (int i = 0; i < 4; ++i)
                br[nf][i] = Bs[p][(l4 + 4 * i) * BPAD + wn + nf * 8 + g];

#pragma unroll
        for (int mf = 0; mf < 4; ++mf)
#pragma unroll
            for (int nf = 0; nf < 4; ++nf) {
                mma_tf32(acc[mf][nf],
                         ar[mf][0][0], ar[mf][1][0], ar[mf][0][1], ar[mf][1][1],
                         br[nf][0], br[nf][1]);
                mma_tf32(acc[mf][nf],
                         ar[mf][0][2], ar[mf][1][2], ar[mf][0][3], ar[mf][1][3],
                         br[nf][2], br[nf][3]);
            }

        if (more) {
            int q = 1 - p;
#pragma unroll
            for (int h = 0; h < 2; ++h) {
                int row = arow_l + h * 64;
                unsigned* dst = &As[q][row * 16];
                int sw = row & 3;
                dst[((0 ^ sw) << 2) + aj] = f2tf(av[h].x);
                dst[((1 ^ sw) << 2) + aj] = f2tf(av[h].y);
                dst[((2 ^ sw) << 2) + aj] = f2tf(av[h].z);
                dst[((3 ^ sw) << 2) + aj] = f2tf(av[h].w);
                unsigned* bd = &Bs[q][(bk + 8 * h) * BPAD + bn];
                bd[0] = f2tf(bv[h].x); bd[1] = f2tf(bv[h].y);
                bd[2] = f2tf(bv[h].z); bd[3] = f2tf(bv[h].w);
            }
        }
        __syncthreads();
    }

    // ---- epilogue ----
#pragma unroll
    for (int mf = 0; mf < 4; ++mf)
#pragma unroll
        for (int rs = 0; rs < 2; ++rs) {
            int rl = wm + mf * 16 + g + rs * 8;
            int gi = row0 + rl;
            if (gi >= cnt) continue;
            int idx = list ? list[e * TT + gi] : gi;
            float* Cr = C + (size_t)idx * N + col0;
            float s = (EPI == 3) ? rowScale[idx] : 1.f;
#pragma unroll
            for (int nf = 0; nf < 4; ++nf) {
                int col = wn + nf * 8 + 2 * l4;
                float v0 = acc[mf][nf][rs * 2 + 0];
                float v1 = acc[mf][nf][rs * 2 + 1];
                if (EPI == 0) {
                    *(float2*)(Cr + col) = make_float2(v0, v1);
                } else if (EPI == 1) {
                    v0 = v0 / (1.f + expf(-v0));
                    v1 = v1 / (1.f + expf(-v1));
                    *(float2*)(Cr + col) = make_float2(v0, v1);
                } else if (EPI == 2) {
                    float2 o = *(float2*)(Cr + col);
                    o.x *= v0; o.y *= v1;
                    *(float2*)(Cr + col) = o;
                } else {
                    *(float2*)(Cr + col) = make_float2(v0 * s, v1 * s);
                }
            }
        }
}

// out[t] += sum_k g_y[t*6+k]
__global__ void add_routed_kernel(float* __restrict__ out) {
    int i = blockIdx.x * blockDim.x + threadIdx.x;
    if (i >= TT * HH / 4) return;
    int t = i / (HH / 4);
    int c = i % (HH / 4);
    float4 o = ((float4*)out)[i];
#pragma unroll
    for (int k = 0; k < KTOP; ++k) {
        float4 v = ((const float4*)(g_y + (size_t)(t * KTOP + k) * HH))[c];
        o.x += v.x; o.y += v.y; o.z += v.z; o.w += v.w;
    }
    ((float4*)out)[i] = o;
}

// ---------------- launch ----------------------------------------------------
extern "C" void kernel_launch(void* const* d_in, const int* in_sizes, int n_in,
                              void* d_out, int out_size)
{
    const float* x      = (const float*)d_in[0];
    const float* wr     = (const float*)d_in[1];
    const float* bias   = (const float*)d_in[2];
    const float* gate_w = (const float*)d_in[3];
    const float* up_w   = (const float*)d_in[4];
    const float* down_w = (const float*)d_in[5];
    const float* shg    = (const float*)d_in[6];
    const float* shu    = (const float*)d_in[7];
    const float* shd    = (const float*)d_in[8];
    float* out = (float*)d_out;

    void *p_act, *p_y, *p_shact, *p_w, *p_cnt, *p_list;
    cudaGetSymbolAddress(&p_act,   g_act);
    cudaGetSymbolAddress(&p_y,     g_y);
    cudaGetSymbolAddress(&p_shact, g_shact);
    cudaGetSymbolAddress(&p_w,     g_topkw);
    cudaGetSymbolAddress(&p_cnt,   g_cnt);
    cudaGetSymbolAddress(&p_list,  g_list);

    zero_cnt_kernel<<<1, 32>>>();
    router_kernel<<<TT / 8, 256>>>(x, wr, bias);

    // routed experts: act = silu(x@gate) * (x@up); y = (act@down) * w
    mma_gemm<1><<<dim3(MI / 128, TT / 128, EE), 256>>>(
        x, gate_w, (float*)p_act, (const int*)p_list, (const int*)p_cnt,
        nullptr, HH, MI, KTOP, 0);
    mma_gemm<2><<<dim3(MI / 128, TT / 128, EE), 256>>>(
        x, up_w, (float*)p_act, (const int*)p_list, (const int*)p_cnt,
        nullptr, HH, MI, KTOP, 0);
    mma_gemm<3><<<dim3(HH / 128, TT / 128, EE), 256>>>(
        (const float*)p_act, down_w, (float*)p_y, (const int*)p_list,
        (const int*)p_cnt, (const float*)p_w, MI, HH, 1, 0);

    // shared experts
    mma_gemm<1><<<dim3(MSHD / 128, TT / 128, 1), 256>>>(
        x, shg, (float*)p_shact, nullptr, nullptr, nullptr, HH, MSHD, 1, TT);
    mma_gemm<2><<<dim3(MSHD / 128, TT / 128, 1), 256>>>(
        x, shu, (float*)p_shact, nullptr, nullptr, nullptr, HH, MSHD, 1, TT);
    mma_gemm<0><<<dim3(HH / 128, TT / 128, 1), 256>>>(
        (const float*)p_shact, shd, out, nullptr, nullptr, nullptr, MSHD, HH, 1, TT);

    add_routed_kernel<<<(TT * HH / 4 + 255) / 256, 256>>>(out);
}

// round 3
// speedup vs baseline: 3.1597x; 1.3238x over previous
#include <cuda_runtime.h>
#include <math.h>

// Problem constants
#define TT   1024
#define HH   2048
#define MI   1408
#define EE   32
#define KTOP 6
#define MSHD 2816
#define NA   (TT * KTOP)

// ---------------- scratch ---------------------------------------------------
__device__ float g_act[(size_t)NA * MI];     // silu(gate)*up per assignment
__device__ float g_shact[(size_t)TT * MSHD]; // shared-expert intermediate
__device__ float g_topkw[NA];
__device__ int   g_cnt[EE];
__device__ int   g_list[EE * TT];

// ---------------- tiny kernels ----------------------------------------------
__global__ void zero_cnt_kernel() {
    if (threadIdx.x < EE) g_cnt[threadIdx.x] = 0;
}

__global__ void router_kernel(const float* __restrict__ x,
                              const float* __restrict__ wr,
                              const float* __restrict__ bias)
{
    __shared__ float s_sfc[8][32];
    __shared__ float s_sc[8][32];
    int warp = threadIdx.x >> 5, lane = threadIdx.x & 31;
    int t = blockIdx.x * 8 + warp;
    const float* xr = x + (size_t)t * HH;

    float acc = 0.f;
#pragma unroll 8
    for (int h = 0; h < HH; ++h) acc = fmaf(xr[h], wr[h * EE + lane], acc);

    float sc = 1.f / (1.f + expf(-acc));
    s_sc[warp][lane]  = sc;
    s_sfc[warp][lane] = sc + bias[lane];
    __syncwarp();

    if (lane == 0) {
        float gsc[8];
#pragma unroll
        for (int g = 0; g < 8; ++g) {
            const float* v = &s_sfc[warp][g * 4];
            float m1 = -INFINITY; int i1 = 0;
            for (int j = 0; j < 4; ++j) if (v[j] > m1) { m1 = v[j]; i1 = j; }
            float m2 = -INFINITY;
            for (int j = 0; j < 4; ++j) if (j != i1 && v[j] > m2) m2 = v[j];
            gsc[g] = m1 + m2;
        }
        unsigned gsel = 0;
        for (int it = 0; it < 4; ++it) {
            float best = -INFINITY; int bi = 0;
            for (int g = 0; g < 8; ++g)
                if (!((gsel >> g) & 1) && gsc[g] > best) { best = gsc[g]; bi = g; }
            gsel |= 1u << bi;
        }
        float msk[32];
        for (int e = 0; e < 32; ++e)
            msk[e] = ((gsel >> (e >> 2)) & 1) ? s_sfc[warp][e] : -INFINITY;
        for (int k = 0; k < KTOP; ++k) {
            float best = -INFINITY; int bi = 0;
            for (int e = 0; e < 32; ++e)
                if (msk[e] > best) { best = msk[e]; bi = e; }
            msk[bi] = -INFINITY;
            int rowid = t * KTOP + k;
            g_topkw[rowid] = s_sc[warp][bi];
            int pos = atomicAdd(&g_cnt[bi], 1);
            g_list[bi * TT + pos] = rowid;
        }
    }
}

// ---------------- mma helpers -----------------------------------------------
__device__ __forceinline__ unsigned f2tf(float f) {
    unsigned r; asm("cvt.rna.tf32.f32 %0, %1;" : "=r"(r) : "f"(f)); return r;
}
__device__ __forceinline__ void mma_tf32(float* c,
    unsigned a0, unsigned a1, unsigned a2, unsigned a3,
    unsigned b0, unsigned b1)
{
    asm volatile(
      "mma.sync.aligned.m16n8k8.row.col.f32.tf32.tf32.f32 "
      "{%0,%1,%2,%3}, {%4,%5,%6,%7}, {%8,%9}, {%0,%1,%2,%3};"
      : "+f"(c[0]), "+f"(c[1]), "+f"(c[2]), "+f"(c[3])
      : "r"(a0), "r"(a1), "r"(a2), "r"(a3), "r"(b0), "r"(b1));
}

// =============================================================================
// Fused gate+up GEMM: act = silu(A@Bg) * (A@Bu)
// Block tile 128x64, BK=16, 8 warps (4m x 2n), warp tile 32x32 per matrix.
// =============================================================================
#define GUP 72   // B smem row stride in words (72 mod 32 == 8 -> conflict-free)

__global__ void __launch_bounds__(256, 2)
gu_gemm(const float* __restrict__ A, const float* __restrict__ Bg_all,
        const float* __restrict__ Bu_all, float* __restrict__ C,
        const int* __restrict__ list, const int* __restrict__ cntArr,
        int K, int N, int rowDiv, int fixedCnt)
{
    int e = blockIdx.z;
    int cnt = cntArr ? cntArr[e] : fixedCnt;
    int row0 = blockIdx.y * 128;
    if (row0 >= cnt) return;
    int col0 = blockIdx.x * 64;
    const float* Bg = Bg_all + (size_t)e * K * N;
    const float* Bu = Bu_all + (size_t)e * K * N;

    __shared__ __align__(16) unsigned As[2][128 * 16];
    __shared__ __align__(16) unsigned Bs[2][2][16 * GUP];

    int tid = threadIdx.x, lane = tid & 31, warp = tid >> 5;
    int l4 = lane & 3, g = lane >> 2;
    int wm = (warp >> 1) * 32;
    int wn = (warp & 1) * 32;

    // A staging map: 512 slots (row, kgroup)
    int arow_l = tid >> 2, aj = tid & 3;
    const float* Arow[2];
#pragma unroll
    for (int h = 0; h < 2; ++h) {
        int gi = row0 + arow_l + h * 64;
        const float* p = nullptr;
        if (gi < cnt) {
            int idx = list ? list[e * TT + gi] : gi;
            p = A + (size_t)(idx / rowDiv) * K;
        }
        Arow[h] = p;
    }
    // B staging map: 16k x 64n per matrix, one float4 per thread per matrix
    int bk = tid >> 4;          // 0..15
    int bn = (tid & 15) * 4;    // 0..60

    float accg[2][4][4], accu[2][4][4];
#pragma unroll
    for (int a = 0; a < 2; ++a)
#pragma unroll
        for (int b = 0; b < 4; ++b)
#pragma unroll
            for (int c = 0; c < 4; ++c) { accg[a][b][c] = 0.f; accu[a][b][c] = 0.f; }

    const int nIter = K / 16;

    // prologue: stage 0
    {
        float4 av[2], vg, vu;
#pragma unroll
        for (int h = 0; h < 2; ++h)
            av[h] = Arow[h] ? *(const float4*)(Arow[h] + 4 * aj)
                            : make_float4(0.f, 0.f, 0.f, 0.f);
        vg = *(const float4*)(Bg + (size_t)bk * N + col0 + bn);
        vu = *(const float4*)(Bu + (size_t)bk * N + col0 + bn);
#pragma unroll
        for (int h = 0; h < 2; ++h) {
            int row = arow_l + h * 64;
            unsigned* dst = &As[0][row * 16];
            int sw = row & 3;
            dst[((0 ^ sw) << 2) + aj] = f2tf(av[h].x);
            dst[((1 ^ sw) << 2) + aj] = f2tf(av[h].y);
            dst[((2 ^ sw) << 2) + aj] = f2tf(av[h].z);
            dst[((3 ^ sw) << 2) + aj] = f2tf(av[h].w);
        }
        *(uint4*)&Bs[0][0][bk * GUP + bn] =
            make_uint4(f2tf(vg.x), f2tf(vg.y), f2tf(vg.z), f2tf(vg.w));
        *(uint4*)&Bs[0][1][bk * GUP + bn] =
            make_uint4(f2tf(vu.x), f2tf(vu.y), f2tf(vu.z), f2tf(vu.w));
    }
    __syncthreads();

    for (int it = 0; it < nIter; ++it) {
        int p = it & 1;
        bool more = (it + 1 < nIter);
        float4 av[2], vg, vu;
        if (more) {
            int k0 = (it + 1) * 16;
#pragma unroll
            for (int h = 0; h < 2; ++h)
                av[h] = Arow[h] ? *(const float4*)(Arow[h] + k0 + 4 * aj)
                                : make_float4(0.f, 0.f, 0.f, 0.f);
            vg = *(const float4*)(Bg + (size_t)(k0 + bk) * N + col0 + bn);
            vu = *(const float4*)(Bu + (size_t)(k0 + bk) * N + col0 + bn);
        }

        // A fragments (one LDS.128 covers all 4 k-groups)
        unsigned ar[2][2][4];
#pragma unroll
        for (int mf = 0; mf < 2; ++mf)
#pragma unroll
            for (int rs = 0; rs < 2; ++rs) {
                int row = wm + mf * 16 + g + rs * 8;
                uint4 v = *(const uint4*)&As[p][row * 16 + ((l4 ^ (row & 3)) << 2)];
                ar[mf][rs][0] = v.x; ar[mf][rs][1] = v.y;
                ar[mf][rs][2] = v.z; ar[mf][rs][3] = v.w;
            }

#pragma unroll
        for (int kh = 0; kh < 2; ++kh) {
            unsigned brg[4][2], bru[4][2];
#pragma unroll
            for (int nf = 0; nf < 4; ++nf)
#pragma unroll
                for (int i = 0; i < 2; ++i) {
                    int krow = l4 + 4 * i + 8 * kh;
                    int nc = wn + nf * 8 + g;
                    brg[nf][i] = Bs[p][0][krow * GUP + nc];
                    bru[nf][i] = Bs[p][1][krow * GUP + nc];
                }
#pragma unroll
            for (int mf = 0; mf < 2; ++mf)
#pragma unroll
                for (int nf = 0; nf < 4; ++nf) {
                    mma_tf32(accg[mf][nf],
                             ar[mf][0][2 * kh], ar[mf][1][2 * kh],
                             ar[mf][0][2 * kh + 1], ar[mf][1][2 * kh + 1],
                             brg[nf][0], brg[nf][1]);
                    mma_tf32(accu[mf][nf],
                             ar[mf][0][2 * kh], ar[mf][1][2 * kh],
                             ar[mf][0][2 * kh + 1], ar[mf][1][2 * kh + 1],
                             bru[nf][0], bru[nf][1]);
                }
        }

        if (more) {
            int q = 1 - p;
#pragma unroll
            for (int h = 0; h < 2; ++h) {
                int row = arow_l + h * 64;
                unsigned* dst = &As[q][row * 16];
                int sw = row & 3;
                dst[((0 ^ sw) << 2) + aj] = f2tf(av[h].x);
                dst[((1 ^ sw) << 2) + aj] = f2tf(av[h].y);
                dst[((2 ^ sw) << 2) + aj] = f2tf(av[h].z);
                dst[((3 ^ sw) << 2) + aj] = f2tf(av[h].w);
            }
            *(uint4*)&Bs[q][0][bk * GUP + bn] =
                make_uint4(f2tf(vg.x), f2tf(vg.y), f2tf(vg.z), f2tf(vg.w));
            *(uint4*)&Bs[q][1][bk * GUP + bn] =
                make_uint4(f2tf(vu.x), f2tf(vu.y), f2tf(vu.z), f2tf(vu.w));
        }
        __syncthreads();
    }

    // epilogue: act = silu(g) * u
#pragma unroll
    for (int mf = 0; mf < 2; ++mf)
#pragma unroll
        for (int rs = 0; rs < 2; ++rs) {
            int rl = wm + mf * 16 + g + rs * 8;
            int gi = row0 + rl;
            if (gi >= cnt) continue;
            int idx = list ? list[e * TT + gi] : gi;
            float* Cr = C + (size_t)idx * N + col0;
#pragma unroll
            for (int nf = 0; nf < 4; ++nf) {
                int col = wn + nf * 8 + 2 * l4;
                float g0 = accg[mf][nf][rs * 2 + 0];
                float g1 = accg[mf][nf][rs * 2 + 1];
                float u0 = accu[mf][nf][rs * 2 + 0];
                float u1 = accu[mf][nf][rs * 2 + 1];
                float s0 = g0 / (1.f + __expf(-g0)) * u0;
                float s1 = g1 / (1.f + __expf(-g1)) * u1;
                *(float2*)(Cr + col) = make_float2(s0, s1);
            }
        }
}

// =============================================================================
// Down GEMM: block tile 128x128, BK=16, 8 warps (2m x 4n), warp tile 64x32.
// ATOMIC=0: C[idx] = v (shared path). ATOMIC=1: out[idx/KTOP] += v*scale[idx].
// =============================================================================
#define DNP 136  // 136 mod 32 == 8 -> conflict-free scalar LDS

template<int ATOMIC>
__global__ void __launch_bounds__(256, 2)
down_gemm(const float* __restrict__ A, const float* __restrict__ Bb,
          float* __restrict__ C,
          const int* __restrict__ list, const int* __restrict__ cntArr,
          const float* __restrict__ rowScale,
          int K, int N, int fixedCnt)
{
    int e = blockIdx.z;
    int cnt = cntArr ? cntArr[e] : fixedCnt;
    int row0 = blockIdx.y * 128;
    if (row0 >= cnt) return;
    int col0 = blockIdx.x * 128;
    const float* B = Bb + (size_t)e * K * N;

    __shared__ __align__(16) unsigned As[2][128 * 16];
    __shared__ __align__(16) unsigned Bs[2][16 * DNP];

    int tid = threadIdx.x, lane = tid & 31, warp = tid >> 5;
    int l4 = lane & 3, g = lane >> 2;
    int wm = (warp & 1) * 64;
    int wn = (warp >> 1) * 32;

    int arow_l = tid >> 2, aj = tid & 3;
    const float* Arow[2];
    int aidx[2];
#pragma unroll
    for (int h = 0; h < 2; ++h) {
        int gi = row0 + arow_l + h * 64;
        const float* p = nullptr;
        int idx = 0;
        if (gi < cnt) {
            idx = list ? list[e * TT + gi] : gi;
            p = A + (size_t)idx * K;
        }
        Arow[h] = p; aidx[h] = idx;
    }
    int bk = tid >> 5;          // 0..7 (two halves)
    int bn = (tid & 31) * 4;

    float acc[4][4][4];
#pragma unroll
    for (int a = 0; a < 4; ++a)
#pragma unroll
        for (int b = 0; b < 4; ++b)
#pragma unroll
            for (int c = 0; c < 4; ++c) acc[a][b][c] = 0.f;

    const int nIter = K / 16;

    {
        float4 av[2], bv[2];
#pragma unroll
        for (int h = 0; h < 2; ++h) {
            av[h] = Arow[h] ? *(const float4*)(Arow[h] + 4 * aj)
                            : make_float4(0.f, 0.f, 0.f, 0.f);
            bv[h] = *(const float4*)(B + (size_t)(bk + 8 * h) * N + col0 + bn);
        }
#pragma unroll
        for (int h = 0; h < 2; ++h) {
            int row = arow_l + h * 64;
            unsigned* dst = &As[0][row * 16];
            int sw = row & 3;
            dst[((0 ^ sw) << 2) + aj] = f2tf(av[h].x);
            dst[((1 ^ sw) << 2) + aj] = f2tf(av[h].y);
            dst[((2 ^ sw) << 2) + aj] = f2tf(av[h].z);
            dst[((3 ^ sw) << 2) + aj] = f2tf(av[h].w);
            *(uint4*)&Bs[0][(bk + 8 * h) * DNP + bn] =
                make_uint4(f2tf(bv[h].x), f2tf(bv[h].y), f2tf(bv[h].z), f2tf(bv[h].w));
        }
    }
    __syncthreads();

    for (int it = 0; it < nIter; ++it) {
        int p = it & 1;
        bool more = (it + 1 < nIter);
        float4 av[2], bv[2];
        if (more) {
            int k0 = (it + 1) * 16;
#pragma unroll
            for (int h = 0; h < 2; ++h) {
                av[h] = Arow[h] ? *(const float4*)(Arow[h] + k0 + 4 * aj)
                                : make_float4(0.f, 0.f, 0.f, 0.f);
                bv[h] = *(const float4*)(B + (size_t)(k0 + bk + 8 * h) * N + col0 + bn);
            }
        }

        unsigned ar[4][2][4];
#pragma unroll
        for (int mf = 0; mf < 4; ++mf)
#pragma unroll
            for (int rs = 0; rs < 2; ++rs) {
                int row = wm + mf * 16 + g + rs * 8;
                uint4 v = *(const uint4*)&As[p][row * 16 + ((l4 ^ (row & 3)) << 2)];
                ar[mf][rs][0] = v.x; ar[mf][rs][1] = v.y;
                ar[mf][rs][2] = v.z; ar[mf][rs][3] = v.w;
            }

#pragma unroll
        for (int kh = 0; kh < 2; ++kh) {
            unsigned br[4][2];
#pragma unroll
            for (int nf = 0; nf < 4; ++nf)
#pragma unroll
                for (int i = 0; i < 2; ++i)
                    br[nf][i] = Bs[p][(l4 + 4 * i + 8 * kh) * DNP + wn + nf * 8 + g];
#pragma unroll
            for (int mf = 0; mf < 4; ++mf)
#pragma unroll
                for (int nf = 0; nf < 4; ++nf)
                    mma_tf32(acc[mf][nf],
                             ar[mf][0][2 * kh], ar[mf][1][2 * kh],
                             ar[mf][0][2 * kh + 1], ar[mf][1][2 * kh + 1],
                             br[nf][0], br[nf][1]);
        }

        if (more) {
            int q = 1 - p;
#pragma unroll
            for (int h = 0; h < 2; ++h) {
                int row = arow_l + h * 64;
                unsigned* dst = &As[q][row * 16];
                int sw = row & 3;
                dst[((0 ^ sw) << 2) + aj] = f2tf(av[h].x);
                dst[((1 ^ sw) << 2) + aj] = f2tf(av[h].y);
                dst[((2 ^ sw) << 2) + aj] = f2tf(av[h].z);
                dst[((3 ^ sw) << 2) + aj] = f2tf(av[h].w);
                *(uint4*)&Bs[q][(bk + 8 * h) * DNP + bn] =
                    make_uint4(f2tf(bv[h].x), f2tf(bv[h].y), f2tf(bv[h].z), f2tf(bv[h].w));
            }
        }
        __syncthreads();
    }

    // epilogue
#pragma unroll
    for (int mf = 0; mf < 4; ++mf)
#pragma unroll
        for (int rs = 0; rs < 2; ++rs) {
            int rl = wm + mf * 16 + g + rs * 8;
            int gi = row0 + rl;
            if (gi >= cnt) continue;
            int idx = list ? list[e * TT + gi] : gi;
            float s = 1.f;
            float* Cr;
            if (ATOMIC) {
                s = rowScale[idx];
                Cr = C + (size_t)(idx / KTOP) * N + col0;
            } else {
                Cr = C + (size_t)idx * N + col0;
            }
#pragma unroll
            for (int nf = 0; nf < 4; ++nf) {
                int col = wn + nf * 8 + 2 * l4;
                float v0 = acc[mf][nf][rs * 2 + 0];
                float v1 = acc[mf][nf][rs * 2 + 1];
                if (ATOMIC) {
                    atomicAdd(Cr + col,     v0 * s);
                    atomicAdd(Cr + col + 1, v1 * s);
                } else {
                    *(float2*)(Cr + col) = make_float2(v0, v1);
                }
            }
        }
}

// ---------------- launch ------------------------------------------------------
extern "C" void kernel_launch(void* const* d_in, const int* in_sizes, int n_in,
                              void* d_out, int out_size)
{
    const float* x      = (const float*)d_in[0];
    const float* wr     = (const float*)d_in[1];
    const float* bias   = (const float*)d_in[2];
    const float* gate_w = (const float*)d_in[3];
    const float* up_w   = (const float*)d_in[4];
    const float* down_w = (const float*)d_in[5];
    const float* shg    = (const float*)d_in[6];
    const float* shu    = (const float*)d_in[7];
    const float* shd    = (const float*)d_in[8];
    float* out = (float*)d_out;

    void *p_act, *p_shact, *p_w, *p_cnt, *p_list;
    cudaGetSymbolAddress(&p_act,   g_act);
    cudaGetSymbolAddress(&p_shact, g_shact);
    cudaGetSymbolAddress(&p_w,     g_topkw);
    cudaGetSymbolAddress(&p_cnt,   g_cnt);
    cudaGetSymbolAddress(&p_list,  g_list);

    zero_cnt_kernel<<<1, 32>>>();
    router_kernel<<<TT / 8, 256>>>(x, wr, bias);

    // routed gate+up fused: act = silu(x@gate) * (x@up)
    gu_gemm<<<dim3(MI / 64, TT / 128, EE), 256>>>(
        x, gate_w, up_w, (float*)p_act,
        (const int*)p_list, (const int*)p_cnt, HH, MI, KTOP, 0);

    // shared gate+up fused
    gu_gemm<<<dim3(MSHD / 64, TT / 128, 1), 256>>>(
        x, shg, shu, (float*)p_shact, nullptr, nullptr, HH, MSHD, 1, TT);

    // shared down: out = shact @ shd   (plain store, covers all of out)
    down_gemm<0><<<dim3(HH / 128, TT / 128, 1), 256>>>(
        (const float*)p_shact, shd, out, nullptr, nullptr, nullptr,
        MSHD, HH, TT);

    // routed down: out[t] += (act @ down_w[e]) * topkw   (atomic reduce)
    down_gemm<1><<<dim3(HH / 128, TT / 128, EE), 256>>>(
        (const float*)p_act, down_w, out, (const int*)p_list,
        (const int*)p_cnt, (const float*)p_w, MI, HH, 0);
}